// round 16
// baseline (speedup 1.0000x reference)
#include <cuda_runtime.h>
#include <cuda_bf16.h>
#include <math.h>

// ---------------- problem constants ----------------
#define TOKS   1024
#define EMB    256
#define NHEADS 8
#define HDIM   32
#define BBATCH 8
#define NLAYER 8
#define HIDDEN 512
#define SCALE_ATTN 0.17677669529663687f   // 32^-0.5
#define LOG2E 1.4426950408889634f
#define QSCALE (SCALE_ATTN * LOG2E)

// ---------------- scratch (device globals; no allocation allowed) ----------------
__device__ float g_y   [BBATCH*TOKS*EMB];            // 8 MB (only first 16K floats used: LN stats)
__device__ float g_qkv [BBATCH*TOKS*3*EMB];          // 24 MB
__device__ float g_o   [BBATCH*TOKS*EMB];            // 8 MB
// g_big is phase-overlaid:
//   attention phase: biasf[h][n][m] = log2e*(rpb + gbias), stored bf16
//   MLP phase:       hid  = g_big[0 .. 4M), hid2 = g_big[4M .. 8M)
__device__ float g_big [NHEADS*TOKS*TOKS];           // 32 MB

__device__ __forceinline__ float gelu_f(float x) {
    return 0.5f * x * (1.0f + erff(x * 0.70710678118654752f));
}

__device__ __forceinline__ unsigned f2tf32(float x) {
    unsigned u; asm("cvt.rna.tf32.f32 %0, %1;" : "=r"(u) : "f"(x)); return u;
}

__device__ __forceinline__ void mma_tf32(float* c,
    unsigned a0, unsigned a1, unsigned a2, unsigned a3,
    unsigned b0, unsigned b1)
{
    asm volatile(
        "mma.sync.aligned.m16n8k8.row.col.f32.tf32.tf32.f32 "
        "{%0,%1,%2,%3},{%4,%5,%6,%7},{%8,%9},{%0,%1,%2,%3};"
        : "+f"(c[0]), "+f"(c[1]), "+f"(c[2]), "+f"(c[3])
        : "r"(a0), "r"(a1), "r"(a2), "r"(a3), "r"(b0), "r"(b1));
}

// ---------------- patch embed ----------------
__global__ void __launch_bounds__(256) patch_embed_k(
    const float* __restrict__ x, const float* __restrict__ pw,
    const float* __restrict__ pb, const float* __restrict__ te,
    float* __restrict__ tok)
{
    int t = blockIdx.x;
    int b = t >> 10, n = t & 1023;
    int pi = n >> 5, pj = n & 31;
    __shared__ float patch[64];
    int tid = threadIdx.x;
    if (tid < 64) {
        int r = tid >> 3, c = tid & 7;
        patch[tid] = x[((size_t)b*256 + (size_t)pi*8 + r)*256 + pj*8 + c];
    }
    __syncthreads();
    float acc = pb[tid] + te[tid];
    const float* w = pw + tid*64;
    #pragma unroll
    for (int k = 0; k < 64; k++) acc = fmaf(w[k], patch[k], acc);
    tok[(size_t)t*EMB + tid] = acc;
}

// ---------------- LN stats: per token (mean, rstd) only ----------------
__global__ void __launch_bounds__(256) lnstats_k(
    const float* __restrict__ in, float2* __restrict__ st)
{
    int warp = threadIdx.x >> 5, lane = threadIdx.x & 31;
    size_t t = (size_t)blockIdx.x*8 + warp;
    const float* row = in + t*EMB;
    float v[8]; float s = 0.f;
    #pragma unroll
    for (int i = 0; i < 8; i++) { v[i] = row[lane + i*32]; s += v[i]; }
    #pragma unroll
    for (int o = 16; o; o >>= 1) s += __shfl_xor_sync(0xffffffffu, s, o);
    float mean = s * (1.f/256.f);
    float var = 0.f;
    #pragma unroll
    for (int i = 0; i < 8; i++) { float d = v[i]-mean; var += d*d; }
    #pragma unroll
    for (int o = 16; o; o >>= 1) var += __shfl_xor_sync(0xffffffffu, var, o);
    if (lane == 0)
        st[t] = make_float2(mean, rsqrtf(var * (1.f/256.f) + 1e-5f));
}

// ---------------- combined attention bias (bf16, pre-scaled by log2e) ----------------
__global__ void __launch_bounds__(256) biasprep_k(
    const float* __restrict__ rt, const float* __restrict__ gb,
    __nv_bfloat16* __restrict__ out)
{
    int n = blockIdx.x, h = blockIdx.y;
    int m0 = threadIdx.x * 4;
    int i1 = n >> 5, j1 = n & 31;
    float4 g = *(const float4*)(gb + (size_t)n*1024 + m0);
    float4 v;
    {
        int m = m0;
        v.x = rt[((i1-(m>>5)+31)*63 + (j1-(m&31)+31))*NHEADS + h] + g.x;
        m = m0+1;
        v.y = rt[((i1-(m>>5)+31)*63 + (j1-(m&31)+31))*NHEADS + h] + g.y;
        m = m0+2;
        v.z = rt[((i1-(m>>5)+31)*63 + (j1-(m&31)+31))*NHEADS + h] + g.z;
        m = m0+3;
        v.w = rt[((i1-(m>>5)+31)*63 + (j1-(m&31)+31))*NHEADS + h] + g.w;
    }
    __nv_bfloat162* o2 = (__nv_bfloat162*)(out + (((size_t)h<<20) | ((size_t)n<<10)) + m0);
    o2[0] = __floats2bfloat162_rn(v.x*LOG2E, v.y*LOG2E);
    o2[1] = __floats2bfloat162_rn(v.z*LOG2E, v.w*LOG2E);
}

// ---------------- tf32 tensor-core GEMM with optional fused LayerNorm on A or B ----
// lnSt != null: apply (v-mean)*rstd*g[k]+beta[k] during staging
//   lnOnB=0 -> on A rows (TRANSA=0 path only; row index = lnStride*z + m-row)
//   lnOnB=1 -> on B rows (row index = lnStride*z + n-row)
template<int TRANSA>
__global__ void __launch_bounds__(256) gemm_tc(
    const float* __restrict__ A, size_t sAb, int lda,
    const float* __restrict__ B, size_t sBb,
    float* __restrict__ C, size_t sCb, int ldc,
    const float* __restrict__ bias, int biasPerM, int doGelu, int doResid,
    const float2* __restrict__ lnSt, const float* __restrict__ lnG,
    const float* __restrict__ lnBe, int lnStride, int lnOnB,
    int K)
{
    __shared__ float As[128][36];
    __shared__ float Bs[64][36];
    A += (size_t)blockIdx.z * sAb;
    B += (size_t)blockIdx.z * sBb;
    C += (size_t)blockIdx.z * sCb;
    int m0 = blockIdx.y * 128, n0 = blockIdx.x * 64;
    int tid = threadIdx.x;
    int warp = tid >> 5, lane = tid & 31;
    int gid = lane >> 2, tig = lane & 3;
    int wm0 = (warp & 3) * 32, wn0 = (warp >> 2) * 32;

    float acc[2][4][4] = {};
    float ar[16], br[8];

    int a_r0 = tid >> 3, a_c = (tid & 7) * 4;     // TRANSA=0: 4 rows x 4 cols
    int a_k  = tid >> 3, a_mb = tid & 7;          // TRANSA=1: 1 col  x 16 rows
    int b_r  = tid >> 2, b_c = (tid & 3) * 8;     // 1 row x 8 cols

    auto loadA = [&](int k0) {
        if (!TRANSA) {
            if (lnSt && !lnOnB) {
                float4 gv = *(const float4*)(lnG + k0 + a_c);
                float4 bv = *(const float4*)(lnBe + k0 + a_c);
                #pragma unroll
                for (int i = 0; i < 4; i++) {
                    int row = m0 + a_r0 + i*32;
                    float2 stv = lnSt[(size_t)lnStride*blockIdx.z + row];
                    float4 v = *(const float4*)(A + (size_t)row*lda + k0 + a_c);
                    ar[i*4+0] = (v.x - stv.x)*stv.y*gv.x + bv.x;
                    ar[i*4+1] = (v.y - stv.x)*stv.y*gv.y + bv.y;
                    ar[i*4+2] = (v.z - stv.x)*stv.y*gv.z + bv.z;
                    ar[i*4+3] = (v.w - stv.x)*stv.y*gv.w + bv.w;
                }
            } else {
                #pragma unroll
                for (int i = 0; i < 4; i++) {
                    float4 v = *(const float4*)(A + (size_t)(m0 + a_r0 + i*32)*lda + k0 + a_c);
                    ar[i*4+0]=v.x; ar[i*4+1]=v.y; ar[i*4+2]=v.z; ar[i*4+3]=v.w;
                }
            }
        } else {
            const float* ak = A + (size_t)(k0 + a_k)*lda + m0;
            #pragma unroll
            for (int i = 0; i < 16; i++) ar[i] = ak[a_mb + i*8];
        }
    };
    auto loadB = [&](int k0) {
        float4 v0 = *(const float4*)(B + (size_t)(n0 + b_r)*K + k0 + b_c);
        float4 v1 = *(const float4*)(B + (size_t)(n0 + b_r)*K + k0 + b_c + 4);
        if (lnSt && lnOnB) {
            float2 stv = lnSt[(size_t)lnStride*blockIdx.z + n0 + b_r];
            float4 g0 = *(const float4*)(lnG + k0 + b_c);
            float4 g1 = *(const float4*)(lnG + k0 + b_c + 4);
            float4 e0 = *(const float4*)(lnBe + k0 + b_c);
            float4 e1 = *(const float4*)(lnBe + k0 + b_c + 4);
            v0.x = (v0.x - stv.x)*stv.y*g0.x + e0.x;
            v0.y = (v0.y - stv.x)*stv.y*g0.y + e0.y;
            v0.z = (v0.z - stv.x)*stv.y*g0.z + e0.z;
            v0.w = (v0.w - stv.x)*stv.y*g0.w + e0.w;
            v1.x = (v1.x - stv.x)*stv.y*g1.x + e1.x;
            v1.y = (v1.y - stv.x)*stv.y*g1.y + e1.y;
            v1.z = (v1.z - stv.x)*stv.y*g1.z + e1.z;
            v1.w = (v1.w - stv.x)*stv.y*g1.w + e1.w;
        }
        br[0]=v0.x; br[1]=v0.y; br[2]=v0.z; br[3]=v0.w;
        br[4]=v1.x; br[5]=v1.y; br[6]=v1.z; br[7]=v1.w;
    };
    auto storeAB = [&]() {
        if (!TRANSA) {
            #pragma unroll
            for (int i = 0; i < 4; i++) {
                int r = a_r0 + i*32;
                As[r][a_c+0] = __uint_as_float(f2tf32(ar[i*4+0]));
                As[r][a_c+1] = __uint_as_float(f2tf32(ar[i*4+1]));
                As[r][a_c+2] = __uint_as_float(f2tf32(ar[i*4+2]));
                As[r][a_c+3] = __uint_as_float(f2tf32(ar[i*4+3]));
            }
        } else {
            #pragma unroll
            for (int i = 0; i < 16; i++)
                As[a_mb + i*8][a_k] = __uint_as_float(f2tf32(ar[i]));
        }
        #pragma unroll
        for (int i = 0; i < 8; i++)
            Bs[b_r][b_c+i] = __uint_as_float(f2tf32(br[i]));
    };

    int niter = K >> 5;
    loadA(0); loadB(0);

    for (int i = 0; i < niter; i++) {
        storeAB();
        __syncthreads();
        if (i + 1 < niter) { loadA((i+1) << 5); loadB((i+1) << 5); }

        #pragma unroll
        for (int kk = 0; kk < 32; kk += 8) {
            unsigned a[2][4], bfr[4][2];
            #pragma unroll
            for (int mi = 0; mi < 2; mi++) {
                int rb = wm0 + mi*16;
                a[mi][0] = __float_as_uint(As[rb+gid  ][kk+tig  ]);
                a[mi][1] = __float_as_uint(As[rb+gid+8][kk+tig  ]);
                a[mi][2] = __float_as_uint(As[rb+gid  ][kk+tig+4]);
                a[mi][3] = __float_as_uint(As[rb+gid+8][kk+tig+4]);
            }
            #pragma unroll
            for (int nf = 0; nf < 4; nf++) {
                bfr[nf][0] = __float_as_uint(Bs[wn0+nf*8+gid][kk+tig  ]);
                bfr[nf][1] = __float_as_uint(Bs[wn0+nf*8+gid][kk+tig+4]);
            }
            #pragma unroll
            for (int mi = 0; mi < 2; mi++)
                #pragma unroll
                for (int nf = 0; nf < 4; nf++)
                    mma_tf32(acc[mi][nf], a[mi][0], a[mi][1], a[mi][2], a[mi][3],
                             bfr[nf][0], bfr[nf][1]);
        }
        __syncthreads();
    }

    #pragma unroll
    for (int mi = 0; mi < 2; mi++) {
        int r0 = m0 + wm0 + mi*16 + gid;
        #pragma unroll
        for (int nf = 0; nf < 4; nf++) {
            int col = n0 + wn0 + nf*8 + 2*tig;
            float v0 = acc[mi][nf][0], v1 = acc[mi][nf][1];
            float v2 = acc[mi][nf][2], v3 = acc[mi][nf][3];
            if (bias) {
                if (biasPerM) {
                    float b0 = bias[r0], b1 = bias[r0+8];
                    v0 += b0; v1 += b0; v2 += b1; v3 += b1;
                } else {
                    float b0 = bias[col], b1 = bias[col+1];
                    v0 += b0; v1 += b1; v2 += b0; v3 += b1;
                }
            }
            if (doGelu) { v0 = gelu_f(v0); v1 = gelu_f(v1); v2 = gelu_f(v2); v3 = gelu_f(v3); }
            float* cl = C + (size_t)r0*ldc + col;
            float* ch = C + (size_t)(r0+8)*ldc + col;
            if (doResid) {
                float2 o0 = *(float2*)cl, o1 = *(float2*)ch;
                v0 += o0.x; v1 += o0.y; v2 += o1.x; v3 += o1.y;
            }
            *(float2*)cl = make_float2(v0, v1);
            *(float2*)ch = make_float2(v2, v3);
        }
    }
}

// ---------------- fused flash attention: tf32 mma, 128-query tiles, no P round-trip,
// ---------------- register-prefetched K/V staging, bf16 bias table, base-2 softmax ----
__global__ void __launch_bounds__(128) attn_k(
    const float* __restrict__ qkv, const __nv_bfloat16* __restrict__ biasf,
    float* __restrict__ o)
{
    __shared__ float Ks[64][36];
    __shared__ float Vs[64][36];
    __shared__ float Qs[128][36];

    int bh = blockIdx.y; int b = bh >> 3, h = bh & 7;
    int n0 = blockIdx.x * 128;

    int tid = threadIdx.x;
    int warp = tid >> 5, lane = tid & 31;
    int gid = lane >> 2, tig = lane & 3;
    int wrow = warp * 32;

    const float* qbase = qkv + (size_t)b*TOKS*768 + h*32;
    const __nv_bfloat16* bias_h = biasf + ((size_t)h << 20);

    // ---- stage Q (128 rows x 32), pre-scaled by SCALE*log2e + tf32 ----
    {
        int c = (tid & 7) * 4, r0 = tid >> 3;
        #pragma unroll
        for (int p = 0; p < 8; p++) {
            int r = r0 + p*16;
            float4 v = *(const float4*)(qbase + (size_t)(n0 + r)*768 + c);
            Qs[r][c+0] = __uint_as_float(f2tf32(v.x * QSCALE));
            Qs[r][c+1] = __uint_as_float(f2tf32(v.y * QSCALE));
            Qs[r][c+2] = __uint_as_float(f2tf32(v.z * QSCALE));
            Qs[r][c+3] = __uint_as_float(f2tf32(v.w * QSCALE));
        }
    }
    __syncthreads();

    // ---- extract Q fragments (loop-invariant) ----
    unsigned qa[2][4][4];
    #pragma unroll
    for (int mi = 0; mi < 2; mi++) {
        int rb = wrow + mi*16;
        #pragma unroll
        for (int kki = 0; kki < 4; kki++) {
            int kk = kki * 8;
            qa[mi][kki][0] = __float_as_uint(Qs[rb+gid  ][kk+tig  ]);
            qa[mi][kki][1] = __float_as_uint(Qs[rb+gid+8][kk+tig  ]);
            qa[mi][kki][2] = __float_as_uint(Qs[rb+gid  ][kk+tig+4]);
            qa[mi][kki][3] = __float_as_uint(Qs[rb+gid+8][kk+tig+4]);
        }
    }

    float m_run[4] = {-1e30f, -1e30f, -1e30f, -1e30f};
    float l_run[4] = {0.f, 0.f, 0.f, 0.f};
    float Oacc[2][4][4] = {};

    // ---- register prefetch of the first K/V tile ----
    int sc = (tid & 7) * 4, sr0 = tid >> 3;
    float4 kvr[4], vvr[4];
    #pragma unroll
    for (int p = 0; p < 4; p++) {
        int r = sr0 + p*16;
        kvr[p] = *(const float4*)(qbase + 256 + (size_t)r*768 + sc);
        vvr[p] = *(const float4*)(qbase + 512 + (size_t)r*768 + sc);
    }

    for (int k0 = 0; k0 < TOKS; k0 += 64) {
        __syncthreads();   // prev PV reads done before restaging K/V
        #pragma unroll
        for (int p = 0; p < 4; p++) {
            int r = sr0 + p*16;
            Ks[r][sc+0] = __uint_as_float(f2tf32(kvr[p].x));
            Ks[r][sc+1] = __uint_as_float(f2tf32(kvr[p].y));
            Ks[r][sc+2] = __uint_as_float(f2tf32(kvr[p].z));
            Ks[r][sc+3] = __uint_as_float(f2tf32(kvr[p].w));
            Vs[r][sc+0] = __uint_as_float(f2tf32(vvr[p].x));
            Vs[r][sc+1] = __uint_as_float(f2tf32(vvr[p].y));
            Vs[r][sc+2] = __uint_as_float(f2tf32(vvr[p].z));
            Vs[r][sc+3] = __uint_as_float(f2tf32(vvr[p].w));
        }
        __syncthreads();
        if (k0 + 64 < TOKS) {
            #pragma unroll
            for (int p = 0; p < 4; p++) {
                int r = k0 + 64 + sr0 + p*16;
                kvr[p] = *(const float4*)(qbase + 256 + (size_t)r*768 + sc);
                vvr[p] = *(const float4*)(qbase + 512 + (size_t)r*768 + sc);
            }
        }

        // ---- S = Q K^T (base-2 logits) ----
        float S[2][8][4] = {};
        #pragma unroll
        for (int kki = 0; kki < 4; kki++) {
            int kk = kki * 8;
            #pragma unroll
            for (int nf = 0; nf < 8; nf++) {
                unsigned b0 = __float_as_uint(Ks[nf*8+gid][kk+tig  ]);
                unsigned b1 = __float_as_uint(Ks[nf*8+gid][kk+tig+4]);
                mma_tf32(S[0][nf], qa[0][kki][0], qa[0][kki][1], qa[0][kki][2], qa[0][kki][3], b0, b1);
                mma_tf32(S[1][nf], qa[1][kki][0], qa[1][kki][1], qa[1][kki][2], qa[1][kki][3], b0, b1);
            }
        }

        // ---- add combined bias (bf16 table, log2e-scaled), row max ----
        float mloc[4] = {-1e30f, -1e30f, -1e30f, -1e30f};
        #pragma unroll
        for (int mi = 0; mi < 2; mi++) {
            int n_a = n0 + wrow + mi*16 + gid;
            const __nv_bfloat16* ba = bias_h + (size_t)n_a*1024 + k0;
            const __nv_bfloat16* bb = ba + 8*1024;
            #pragma unroll
            for (int nf = 0; nf < 8; nf++) {
                int m = nf*8 + 2*tig;
                float2 ga = __bfloat1622float2(*(const __nv_bfloat162*)(ba + m));
                float2 gc = __bfloat1622float2(*(const __nv_bfloat162*)(bb + m));
                S[mi][nf][0] += ga.x; S[mi][nf][1] += ga.y;
                S[mi][nf][2] += gc.x; S[mi][nf][3] += gc.y;
                mloc[2*mi  ] = fmaxf(mloc[2*mi  ], fmaxf(S[mi][nf][0], S[mi][nf][1]));
                mloc[2*mi+1] = fmaxf(mloc[2*mi+1], fmaxf(S[mi][nf][2], S[mi][nf][3]));
            }
        }
        #pragma unroll
        for (int off = 1; off < 4; off <<= 1) {
            #pragma unroll
            for (int j = 0; j < 4; j++)
                mloc[j] = fmaxf(mloc[j], __shfl_xor_sync(0xffffffffu, mloc[j], off));
        }

        // ---- online softmax, base-2 (S -> tf32 P in place) ----
        float mn[4], al[4], sl[4] = {0.f, 0.f, 0.f, 0.f};
        #pragma unroll
        for (int j = 0; j < 4; j++) {
            mn[j] = fmaxf(m_run[j], mloc[j]);
            al[j] = exp2f(m_run[j] - mn[j]);
        }
        #pragma unroll
        for (int mi = 0; mi < 2; mi++) {
            #pragma unroll
            for (int nf = 0; nf < 8; nf++) {
                float e0 = exp2f(S[mi][nf][0] - mn[2*mi]);
                float e1 = exp2f(S[mi][nf][1] - mn[2*mi]);
                float e2 = exp2f(S[mi][nf][2] - mn[2*mi+1]);
                float e3 = exp2f(S[mi][nf][3] - mn[2*mi+1]);
                sl[2*mi  ] += e0 + e1;
                sl[2*mi+1] += e2 + e3;
                S[mi][nf][0] = __uint_as_float(f2tf32(e0));
                S[mi][nf][1] = __uint_as_float(f2tf32(e1));
                S[mi][nf][2] = __uint_as_float(f2tf32(e2));
                S[mi][nf][3] = __uint_as_float(f2tf32(e3));
            }
        }
        #pragma unroll
        for (int off = 1; off < 4; off <<= 1) {
            #pragma unroll
            for (int j = 0; j < 4; j++)
                sl[j] += __shfl_xor_sync(0xffffffffu, sl[j], off);
        }
        #pragma unroll
        for (int j = 0; j < 4; j++) {
            l_run[j] = l_run[j]*al[j] + sl[j];
            m_run[j] = mn[j];
        }
        #pragma unroll
        for (int mi = 0; mi < 2; mi++)
            #pragma unroll
            for (int df = 0; df < 4; df++) {
                Oacc[mi][df][0] *= al[2*mi];   Oacc[mi][df][1] *= al[2*mi];
                Oacc[mi][df][2] *= al[2*mi+1]; Oacc[mi][df][3] *= al[2*mi+1];
            }

        // ---- O += P @ V : S C-frags used directly as A-frags, V rows permuted ----
        #pragma unroll
        for (int nf = 0; nf < 8; nf++) {
            int kk = nf * 8;
            unsigned vb0[4], vb1[4];
            #pragma unroll
            for (int df = 0; df < 4; df++) {
                vb0[df] = __float_as_uint(Vs[kk + 2*tig    ][df*8+gid]);
                vb1[df] = __float_as_uint(Vs[kk + 2*tig + 1][df*8+gid]);
            }
            #pragma unroll
            for (int mi = 0; mi < 2; mi++) {
                unsigned a0 = __float_as_uint(S[mi][nf][0]);
                unsigned a1 = __float_as_uint(S[mi][nf][2]);
                unsigned a2 = __float_as_uint(S[mi][nf][1]);
                unsigned a3 = __float_as_uint(S[mi][nf][3]);
                #pragma unroll
                for (int df = 0; df < 4; df++)
                    mma_tf32(Oacc[mi][df], a0, a1, a2, a3, vb0[df], vb1[df]);
            }
        }
    }

    // ---- epilogue ----
    #pragma unroll
    for (int j = 0; j < 4; j++) {
        int mi = j >> 1, half = j & 1;
        float inv = 1.f / l_run[j];
        int row = n0 + wrow + mi*16 + gid + half*8;
        float* op = o + (size_t)(b*TOKS + row)*EMB + h*32;
        #pragma unroll
        for (int df = 0; df < 4; df++) {
            *(float2*)(op + df*8 + 2*tig) =
                make_float2(Oacc[mi][df][half*2]*inv, Oacc[mi][df][half*2+1]*inv);
        }
    }
}

// ---------------- depthwise 3x3 dilation-2 conv + bias + gelu ----------------
__global__ void __launch_bounds__(256) dwconv_k(
    const float* __restrict__ hid, const float* __restrict__ wd,
    const float* __restrict__ bd, float* __restrict__ out)
{
    int bc = blockIdx.x;
    int c = bc & 511;
    __shared__ float t[32][32];
    const float* in = hid + (size_t)bc*1024;
    int tid = threadIdx.x;
    #pragma unroll
    for (int i = 0; i < 4; i++) { int p = tid + i*256; t[p>>5][p&31] = in[p]; }
    __syncthreads();
    float w[9];
    #pragma unroll
    for (int i = 0; i < 9; i++) w[i] = wd[c*9 + i];
    float bias = bd[c];
    #pragma unroll
    for (int i = 0; i < 4; i++) {
        int p = tid + i*256; int r = p >> 5, col = p & 31;
        float s = bias;
        #pragma unroll
        for (int u = 0; u < 3; u++)
            #pragma unroll
            for (int v = 0; v < 3; v++) {
                int rr = r + (u-1)*2, cc = col + (v-1)*2;
                if (rr >= 0 && rr < 32 && cc >= 0 && cc < 32)
                    s = fmaf(t[rr][cc], w[u*3+v], s);
            }
        out[(size_t)bc*1024 + p] = gelu_f(s);
    }
}

// ---------------- orchestration ----------------
extern "C" void kernel_launch(void* const* d_in, const int* in_sizes, int n_in,
                              void* d_out, int out_size)
{
    const float* x     = (const float*)d_in[0];
    const float* pw    = (const float*)d_in[1];
    const float* pb    = (const float*)d_in[2];
    const float* te    = (const float*)d_in[3];
    const float* qkvw  = (const float*)d_in[4];
    const float* projw = (const float*)d_in[5];
    const float* projb = (const float*)d_in[6];
    const float* ln1g  = (const float*)d_in[7];
    const float* ln1b  = (const float*)d_in[8];
    const float* ln2g  = (const float*)d_in[9];
    const float* ln2b  = (const float*)d_in[10];
    const float* rpbt  = (const float*)d_in[11];
    const float* gb    = (const float*)d_in[12];
    const float* pw1w  = (const float*)d_in[13];
    const float* pw1b  = (const float*)d_in[14];
    const float* dww   = (const float*)d_in[15];
    const float* dwb   = (const float*)d_in[16];
    const float* pw2w  = (const float*)d_in[17];
    const float* pw2b  = (const float*)d_in[18];
    float* tok = (float*)d_out;

    float *yb, *qkvb, *ob, *big;
    cudaGetSymbolAddress((void**)&yb,   g_y);
    cudaGetSymbolAddress((void**)&qkvb, g_qkv);
    cudaGetSymbolAddress((void**)&ob,   g_o);
    cudaGetSymbolAddress((void**)&big,  g_big);
    float2* st = (float2*)yb;                        // LN stats (16K floats of g_y)
    __nv_bfloat16* biasf = (__nv_bfloat16*)big;      // attention phase (16 MB used)
    float* hid   = big;                              // MLP phase (first half)
    float* hid2  = big + (size_t)BBATCH*HIDDEN*TOKS; // MLP phase (second half)

    patch_embed_k<<<BBATCH*TOKS, 256>>>(x, pw, pb, te, tok);

    for (int l = 0; l < NLAYER; l++) {
        // --- attention phase (g_big = bf16 biasf) ---
        biasprep_k<<<dim3(1024, 8), 256>>>(
            rpbt + (size_t)l*3969*NHEADS, gb + (size_t)l*1024*1024, biasf);
        lnstats_k<<<1024, 256>>>(tok, st);
        // qkv = LN1(tok) @ qkv_w^T : M=8192, N=768, K=256 (LN fused into A staging)
        gemm_tc<0><<<dim3(12, 64, 1), 256>>>(
            tok, 0, EMB,
            qkvw + (size_t)l*768*EMB, 0,
            qkvb, 0, 768, nullptr, 0, 0, 0,
            st, ln1g + l*EMB, ln1b + l*EMB, 0, 0, EMB);
        attn_k<<<dim3(8, 64), 128>>>(qkvb, biasf, ob);
        // tok += o @ proj_w^T + proj_b : M=8192, N=256, K=256
        gemm_tc<0><<<dim3(4, 64, 1), 256>>>(
            ob, 0, EMB,
            projw + (size_t)l*EMB*EMB, 0,
            tok, 0, EMB, projb + l*EMB, 0, 0, 1,
            nullptr, nullptr, nullptr, 0, 0, EMB);

        // --- MLP phase (g_big = hid | hid2; biasf is dead now) ---
        lnstats_k<<<1024, 256>>>(tok, st);
        // hid[b][c][n] = gelu(W1·LN2(tok)^T + b1[c]) : per-batch M=512, N=1024, K=256
        gemm_tc<0><<<dim3(16, 4, BBATCH), 256>>>(
            pw1w + (size_t)l*HIDDEN*EMB, 0, EMB,
            tok, (size_t)TOKS*EMB,
            hid, (size_t)HIDDEN*TOKS, TOKS, pw1b + l*HIDDEN, 1, 1, 0,
            st, ln2g + l*EMB, ln2b + l*EMB, TOKS, 1, EMB);
        dwconv_k<<<BBATCH*HIDDEN, 256>>>(hid, dww + (size_t)l*HIDDEN*9, dwb + l*HIDDEN, hid2);
        // tok += hid2^T · W2^T + b2 : per-batch M=1024, N=256, K=512 (A transposed)
        gemm_tc<1><<<dim3(4, 8, BBATCH), 256>>>(
            hid2, (size_t)HIDDEN*TOKS, TOKS,
            pw2w + (size_t)l*EMB*HIDDEN, 0,
            tok, (size_t)TOKS*EMB, EMB, pw2b + l*EMB, 0, 0, 1,
            nullptr, nullptr, nullptr, 0, 0, HIDDEN);
    }
}

// round 17
// speedup vs baseline: 1.0413x; 1.0413x over previous
#include <cuda_runtime.h>
#include <cuda_bf16.h>
#include <math.h>

// ---------------- problem constants ----------------
#define TOKS   1024
#define EMB    256
#define NHEADS 8
#define HDIM   32
#define BBATCH 8
#define NLAYER 8
#define HIDDEN 512
#define SCALE_ATTN 0.17677669529663687f   // 32^-0.5
#define LOG2E 1.4426950408889634f
#define QSCALE (SCALE_ATTN * LOG2E)

// ---------------- scratch (device globals; no allocation allowed) ----------------
__device__ float g_y   [BBATCH*TOKS*EMB];            // 8 MB
__device__ float g_qkv [BBATCH*TOKS*3*EMB];          // 24 MB
__device__ float g_o   [BBATCH*TOKS*EMB];            // 8 MB
// g_big is phase-overlaid:
//   attention phase: biasf[h][n][m] = log2e*(rpb + gbias), stored bf16
//   MLP phase:       hid  = g_big[0 .. 4M), hid2 = g_big[4M .. 8M)
__device__ float g_big [NHEADS*TOKS*TOKS];           // 32 MB

__device__ __forceinline__ float gelu_f(float x) {
    return 0.5f * x * (1.0f + erff(x * 0.70710678118654752f));
}

__device__ __forceinline__ unsigned f2tf32(float x) {
    unsigned u; asm("cvt.rna.tf32.f32 %0, %1;" : "=r"(u) : "f"(x)); return u;
}

__device__ __forceinline__ void mma_tf32(float* c,
    unsigned a0, unsigned a1, unsigned a2, unsigned a3,
    unsigned b0, unsigned b1)
{
    asm volatile(
        "mma.sync.aligned.m16n8k8.row.col.f32.tf32.tf32.f32 "
        "{%0,%1,%2,%3},{%4,%5,%6,%7},{%8,%9},{%0,%1,%2,%3};"
        : "+f"(c[0]), "+f"(c[1]), "+f"(c[2]), "+f"(c[3])
        : "r"(a0), "r"(a1), "r"(a2), "r"(a3), "r"(b0), "r"(b1));
}

// ---------------- patch embed ----------------
__global__ void __launch_bounds__(256) patch_embed_k(
    const float* __restrict__ x, const float* __restrict__ pw,
    const float* __restrict__ pb, const float* __restrict__ te,
    float* __restrict__ tok)
{
    int t = blockIdx.x;
    int b = t >> 10, n = t & 1023;
    int pi = n >> 5, pj = n & 31;
    __shared__ float patch[64];
    int tid = threadIdx.x;
    if (tid < 64) {
        int r = tid >> 3, c = tid & 7;
        patch[tid] = x[((size_t)b*256 + (size_t)pi*8 + r)*256 + pj*8 + c];
    }
    __syncthreads();
    float acc = pb[tid] + te[tid];
    const float* w = pw + tid*64;
    #pragma unroll
    for (int k = 0; k < 64; k++) acc = fmaf(w[k], patch[k], acc);
    tok[(size_t)t*EMB + tid] = acc;
}

// ---------------- layernorm ----------------
__global__ void __launch_bounds__(256) layernorm_k(
    const float* __restrict__ in, const float* __restrict__ g,
    const float* __restrict__ bta, float* __restrict__ out)
{
    int warp = threadIdx.x >> 5, lane = threadIdx.x & 31;
    size_t t = (size_t)blockIdx.x*8 + warp;
    const float* row = in + t*EMB;
    float v[8]; float s = 0.f;
    #pragma unroll
    for (int i = 0; i < 8; i++) { v[i] = row[lane + i*32]; s += v[i]; }
    #pragma unroll
    for (int o = 16; o; o >>= 1) s += __shfl_xor_sync(0xffffffffu, s, o);
    float mean = s * (1.f/256.f);
    float var = 0.f;
    #pragma unroll
    for (int i = 0; i < 8; i++) { float d = v[i]-mean; var += d*d; }
    #pragma unroll
    for (int o = 16; o; o >>= 1) var += __shfl_xor_sync(0xffffffffu, var, o);
    float r = rsqrtf(var * (1.f/256.f) + 1e-5f);
    float* orow = out + t*EMB;
    #pragma unroll
    for (int i = 0; i < 8; i++) {
        int c = lane + i*32;
        orow[c] = (v[i]-mean)*r*g[c] + bta[c];
    }
}

// ---------------- combined attention bias (bf16, pre-scaled by log2e) ----------------
__global__ void __launch_bounds__(256) biasprep_k(
    const float* __restrict__ rt, const float* __restrict__ gb,
    __nv_bfloat16* __restrict__ out)
{
    int n = blockIdx.x, h = blockIdx.y;
    int m0 = threadIdx.x * 4;
    int i1 = n >> 5, j1 = n & 31;
    float4 g = *(const float4*)(gb + (size_t)n*1024 + m0);
    float4 v;
    {
        int m = m0;
        v.x = rt[((i1-(m>>5)+31)*63 + (j1-(m&31)+31))*NHEADS + h] + g.x;
        m = m0+1;
        v.y = rt[((i1-(m>>5)+31)*63 + (j1-(m&31)+31))*NHEADS + h] + g.y;
        m = m0+2;
        v.z = rt[((i1-(m>>5)+31)*63 + (j1-(m&31)+31))*NHEADS + h] + g.z;
        m = m0+3;
        v.w = rt[((i1-(m>>5)+31)*63 + (j1-(m&31)+31))*NHEADS + h] + g.w;
    }
    __nv_bfloat162* o2 = (__nv_bfloat162*)(out + (((size_t)h<<20) | ((size_t)n<<10)) + m0);
    o2[0] = __floats2bfloat162_rn(v.x*LOG2E, v.y*LOG2E);
    o2[1] = __floats2bfloat162_rn(v.z*LOG2E, v.w*LOG2E);
}

// ---------------- tf32 tensor-core GEMM (R14-proven) ----------------
// Register prefetch of next K-chunk + double-buffered kk fragments.
template<int TRANSA>
__global__ void __launch_bounds__(256) gemm_tc(
    const float* __restrict__ A, size_t sAb, int lda,
    const float* __restrict__ B, size_t sBb,
    float* __restrict__ C, size_t sCb, int ldc,
    const float* __restrict__ bias, int biasPerM, int doGelu, int doResid,
    int K)
{
    __shared__ float As[128][36];
    __shared__ float Bs[64][36];
    A += (size_t)blockIdx.z * sAb;
    B += (size_t)blockIdx.z * sBb;
    C += (size_t)blockIdx.z * sCb;
    int m0 = blockIdx.y * 128, n0 = blockIdx.x * 64;
    int tid = threadIdx.x;
    int warp = tid >> 5, lane = tid & 31;
    int gid = lane >> 2, tig = lane & 3;
    int wm0 = (warp & 3) * 32, wn0 = (warp >> 2) * 32;

    float acc[2][4][4] = {};
    float ar[16], br[8];

    int a_r0 = tid >> 3, a_c = (tid & 7) * 4;     // TRANSA=0: 4 rows x 4 cols
    int a_k  = tid >> 3, a_mb = tid & 7;          // TRANSA=1: 1 col  x 16 rows
    int b_r  = tid >> 2, b_c = (tid & 3) * 8;     // 1 row x 8 cols

    auto loadA = [&](int k0) {
        if (!TRANSA) {
            #pragma unroll
            for (int i = 0; i < 4; i++) {
                float4 v = *(const float4*)(A + (size_t)(m0 + a_r0 + i*32)*lda + k0 + a_c);
                ar[i*4+0]=v.x; ar[i*4+1]=v.y; ar[i*4+2]=v.z; ar[i*4+3]=v.w;
            }
        } else {
            const float* ak = A + (size_t)(k0 + a_k)*lda + m0;
            #pragma unroll
            for (int i = 0; i < 16; i++) ar[i] = ak[a_mb + i*8];
        }
    };
    auto loadB = [&](int k0) {
        float4 v0 = *(const float4*)(B + (size_t)(n0 + b_r)*K + k0 + b_c);
        float4 v1 = *(const float4*)(B + (size_t)(n0 + b_r)*K + k0 + b_c + 4);
        br[0]=v0.x; br[1]=v0.y; br[2]=v0.z; br[3]=v0.w;
        br[4]=v1.x; br[5]=v1.y; br[6]=v1.z; br[7]=v1.w;
    };
    auto storeAB = [&]() {
        if (!TRANSA) {
            #pragma unroll
            for (int i = 0; i < 4; i++) {
                int r = a_r0 + i*32;
                As[r][a_c+0] = __uint_as_float(f2tf32(ar[i*4+0]));
                As[r][a_c+1] = __uint_as_float(f2tf32(ar[i*4+1]));
                As[r][a_c+2] = __uint_as_float(f2tf32(ar[i*4+2]));
                As[r][a_c+3] = __uint_as_float(f2tf32(ar[i*4+3]));
            }
        } else {
            #pragma unroll
            for (int i = 0; i < 16; i++)
                As[a_mb + i*8][a_k] = __uint_as_float(f2tf32(ar[i]));
        }
        #pragma unroll
        for (int i = 0; i < 8; i++)
            Bs[b_r][b_c+i] = __uint_as_float(f2tf32(br[i]));
    };

    // double-buffered kk fragments
    unsigned af[2][2][4], bf[2][4][2];
    auto ldfrag = [&](int buf, int kk) {
        #pragma unroll
        for (int mi = 0; mi < 2; mi++) {
            int rb = wm0 + mi*16;
            af[buf][mi][0] = __float_as_uint(As[rb+gid  ][kk+tig  ]);
            af[buf][mi][1] = __float_as_uint(As[rb+gid+8][kk+tig  ]);
            af[buf][mi][2] = __float_as_uint(As[rb+gid  ][kk+tig+4]);
            af[buf][mi][3] = __float_as_uint(As[rb+gid+8][kk+tig+4]);
        }
        #pragma unroll
        for (int nf = 0; nf < 4; nf++) {
            bf[buf][nf][0] = __float_as_uint(Bs[wn0+nf*8+gid][kk+tig  ]);
            bf[buf][nf][1] = __float_as_uint(Bs[wn0+nf*8+gid][kk+tig+4]);
        }
    };

    int niter = K >> 5;
    loadA(0); loadB(0);

    for (int i = 0; i < niter; i++) {
        storeAB();
        __syncthreads();
        if (i + 1 < niter) { loadA((i+1) << 5); loadB((i+1) << 5); }

        ldfrag(0, 0);
        #pragma unroll
        for (int kki = 0; kki < 4; kki++) {
            if (kki < 3) ldfrag((kki + 1) & 1, (kki + 1) * 8);
            int cb = kki & 1;
            #pragma unroll
            for (int mi = 0; mi < 2; mi++)
                #pragma unroll
                for (int nf = 0; nf < 4; nf++)
                    mma_tf32(acc[mi][nf],
                             af[cb][mi][0], af[cb][mi][1], af[cb][mi][2], af[cb][mi][3],
                             bf[cb][nf][0], bf[cb][nf][1]);
        }
        __syncthreads();
    }

    #pragma unroll
    for (int mi = 0; mi < 2; mi++) {
        int r0 = m0 + wm0 + mi*16 + gid;
        #pragma unroll
        for (int nf = 0; nf < 4; nf++) {
            int col = n0 + wn0 + nf*8 + 2*tig;
            float v0 = acc[mi][nf][0], v1 = acc[mi][nf][1];
            float v2 = acc[mi][nf][2], v3 = acc[mi][nf][3];
            if (bias) {
                if (biasPerM) {
                    float b0 = bias[r0], b1 = bias[r0+8];
                    v0 += b0; v1 += b0; v2 += b1; v3 += b1;
                } else {
                    float b0 = bias[col], b1 = bias[col+1];
                    v0 += b0; v1 += b1; v2 += b0; v3 += b1;
                }
            }
            if (doGelu) { v0 = gelu_f(v0); v1 = gelu_f(v1); v2 = gelu_f(v2); v3 = gelu_f(v3); }
            float* cl = C + (size_t)r0*ldc + col;
            float* ch = C + (size_t)(r0+8)*ldc + col;
            if (doResid) {
                float2 o0 = *(float2*)cl, o1 = *(float2*)ch;
                v0 += o0.x; v1 += o0.y; v2 += o1.x; v3 += o1.y;
            }
            *(float2*)cl = make_float2(v0, v1);
            *(float2*)ch = make_float2(v2, v3);
        }
    }
}

// ---------------- fused flash attention: tf32 mma, 128-query tiles, no P round-trip,
// ---------------- register-prefetched K/V staging, bf16 bias table, base-2 softmax ----
__global__ void __launch_bounds__(128) attn_k(
    const float* __restrict__ qkv, const __nv_bfloat16* __restrict__ biasf,
    float* __restrict__ o)
{
    __shared__ float Ks[64][36];
    __shared__ float Vs[64][36];
    __shared__ float Qs[128][36];

    int bh = blockIdx.y; int b = bh >> 3, h = bh & 7;
    int n0 = blockIdx.x * 128;

    int tid = threadIdx.x;
    int warp = tid >> 5, lane = tid & 31;
    int gid = lane >> 2, tig = lane & 3;
    int wrow = warp * 32;

    const float* qbase = qkv + (size_t)b*TOKS*768 + h*32;
    const __nv_bfloat16* bias_h = biasf + ((size_t)h << 20);

    // ---- stage Q (128 rows x 32), pre-scaled by SCALE*log2e + tf32 ----
    {
        int c = (tid & 7) * 4, r0 = tid >> 3;
        #pragma unroll
        for (int p = 0; p < 8; p++) {
            int r = r0 + p*16;
            float4 v = *(const float4*)(qbase + (size_t)(n0 + r)*768 + c);
            Qs[r][c+0] = __uint_as_float(f2tf32(v.x * QSCALE));
            Qs[r][c+1] = __uint_as_float(f2tf32(v.y * QSCALE));
            Qs[r][c+2] = __uint_as_float(f2tf32(v.z * QSCALE));
            Qs[r][c+3] = __uint_as_float(f2tf32(v.w * QSCALE));
        }
    }
    __syncthreads();

    // ---- extract Q fragments (loop-invariant) ----
    unsigned qa[2][4][4];
    #pragma unroll
    for (int mi = 0; mi < 2; mi++) {
        int rb = wrow + mi*16;
        #pragma unroll
        for (int kki = 0; kki < 4; kki++) {
            int kk = kki * 8;
            qa[mi][kki][0] = __float_as_uint(Qs[rb+gid  ][kk+tig  ]);
            qa[mi][kki][1] = __float_as_uint(Qs[rb+gid+8][kk+tig  ]);
            qa[mi][kki][2] = __float_as_uint(Qs[rb+gid  ][kk+tig+4]);
            qa[mi][kki][3] = __float_as_uint(Qs[rb+gid+8][kk+tig+4]);
        }
    }

    float m_run[4] = {-1e30f, -1e30f, -1e30f, -1e30f};
    float l_run[4] = {0.f, 0.f, 0.f, 0.f};
    float Oacc[2][4][4] = {};

    // ---- register prefetch of the first K/V tile ----
    int sc = (tid & 7) * 4, sr0 = tid >> 3;
    float4 kvr[4], vvr[4];
    #pragma unroll
    for (int p = 0; p < 4; p++) {
        int r = sr0 + p*16;
        kvr[p] = *(const float4*)(qbase + 256 + (size_t)r*768 + sc);
        vvr[p] = *(const float4*)(qbase + 512 + (size_t)r*768 + sc);
    }

    for (int k0 = 0; k0 < TOKS; k0 += 64) {
        __syncthreads();   // prev PV reads done before restaging K/V
        #pragma unroll
        for (int p = 0; p < 4; p++) {
            int r = sr0 + p*16;
            Ks[r][sc+0] = __uint_as_float(f2tf32(kvr[p].x));
            Ks[r][sc+1] = __uint_as_float(f2tf32(kvr[p].y));
            Ks[r][sc+2] = __uint_as_float(f2tf32(kvr[p].z));
            Ks[r][sc+3] = __uint_as_float(f2tf32(kvr[p].w));
            Vs[r][sc+0] = __uint_as_float(f2tf32(vvr[p].x));
            Vs[r][sc+1] = __uint_as_float(f2tf32(vvr[p].y));
            Vs[r][sc+2] = __uint_as_float(f2tf32(vvr[p].z));
            Vs[r][sc+3] = __uint_as_float(f2tf32(vvr[p].w));
        }
        __syncthreads();
        if (k0 + 64 < TOKS) {
            #pragma unroll
            for (int p = 0; p < 4; p++) {
                int r = k0 + 64 + sr0 + p*16;
                kvr[p] = *(const float4*)(qbase + 256 + (size_t)r*768 + sc);
                vvr[p] = *(const float4*)(qbase + 512 + (size_t)r*768 + sc);
            }
        }

        // ---- S = Q K^T (base-2 logits) ----
        float S[2][8][4] = {};
        #pragma unroll
        for (int kki = 0; kki < 4; kki++) {
            int kk = kki * 8;
            #pragma unroll
            for (int nf = 0; nf < 8; nf++) {
                unsigned b0 = __float_as_uint(Ks[nf*8+gid][kk+tig  ]);
                unsigned b1 = __float_as_uint(Ks[nf*8+gid][kk+tig+4]);
                mma_tf32(S[0][nf], qa[0][kki][0], qa[0][kki][1], qa[0][kki][2], qa[0][kki][3], b0, b1);
                mma_tf32(S[1][nf], qa[1][kki][0], qa[1][kki][1], qa[1][kki][2], qa[1][kki][3], b0, b1);
            }
        }

        // ---- add combined bias (bf16 table, log2e-scaled), row max ----
        float mloc[4] = {-1e30f, -1e30f, -1e30f, -1e30f};
        #pragma unroll
        for (int mi = 0; mi < 2; mi++) {
            int n_a = n0 + wrow + mi*16 + gid;
            const __nv_bfloat16* ba = bias_h + (size_t)n_a*1024 + k0;
            const __nv_bfloat16* bb = ba + 8*1024;
            #pragma unroll
            for (int nf = 0; nf < 8; nf++) {
                int m = nf*8 + 2*tig;
                float2 ga = __bfloat1622float2(*(const __nv_bfloat162*)(ba + m));
                float2 gc = __bfloat1622float2(*(const __nv_bfloat162*)(bb + m));
                S[mi][nf][0] += ga.x; S[mi][nf][1] += ga.y;
                S[mi][nf][2] += gc.x; S[mi][nf][3] += gc.y;
                mloc[2*mi  ] = fmaxf(mloc[2*mi  ], fmaxf(S[mi][nf][0], S[mi][nf][1]));
                mloc[2*mi+1] = fmaxf(mloc[2*mi+1], fmaxf(S[mi][nf][2], S[mi][nf][3]));
            }
        }
        #pragma unroll
        for (int off = 1; off < 4; off <<= 1) {
            #pragma unroll
            for (int j = 0; j < 4; j++)
                mloc[j] = fmaxf(mloc[j], __shfl_xor_sync(0xffffffffu, mloc[j], off));
        }

        // ---- online softmax, base-2 (S -> tf32 P in place) ----
        float mn[4], al[4], sl[4] = {0.f, 0.f, 0.f, 0.f};
        #pragma unroll
        for (int j = 0; j < 4; j++) {
            mn[j] = fmaxf(m_run[j], mloc[j]);
            al[j] = exp2f(m_run[j] - mn[j]);
        }
        #pragma unroll
        for (int mi = 0; mi < 2; mi++) {
            #pragma unroll
            for (int nf = 0; nf < 8; nf++) {
                float e0 = exp2f(S[mi][nf][0] - mn[2*mi]);
                float e1 = exp2f(S[mi][nf][1] - mn[2*mi]);
                float e2 = exp2f(S[mi][nf][2] - mn[2*mi+1]);
                float e3 = exp2f(S[mi][nf][3] - mn[2*mi+1]);
                sl[2*mi  ] += e0 + e1;
                sl[2*mi+1] += e2 + e3;
                S[mi][nf][0] = __uint_as_float(f2tf32(e0));
                S[mi][nf][1] = __uint_as_float(f2tf32(e1));
                S[mi][nf][2] = __uint_as_float(f2tf32(e2));
                S[mi][nf][3] = __uint_as_float(f2tf32(e3));
            }
        }
        #pragma unroll
        for (int off = 1; off < 4; off <<= 1) {
            #pragma unroll
            for (int j = 0; j < 4; j++)
                sl[j] += __shfl_xor_sync(0xffffffffu, sl[j], off);
        }
        #pragma unroll
        for (int j = 0; j < 4; j++) {
            l_run[j] = l_run[j]*al[j] + sl[j];
            m_run[j] = mn[j];
        }
        #pragma unroll
        for (int mi = 0; mi < 2; mi++)
            #pragma unroll
            for (int df = 0; df < 4; df++) {
                Oacc[mi][df][0] *= al[2*mi];   Oacc[mi][df][1] *= al[2*mi];
                Oacc[mi][df][2] *= al[2*mi+1]; Oacc[mi][df][3] *= al[2*mi+1];
            }

        // ---- O += P @ V : S C-frags used directly as A-frags, V rows permuted ----
        #pragma unroll
        for (int nf = 0; nf < 8; nf++) {
            int kk = nf * 8;
            unsigned vb0[4], vb1[4];
            #pragma unroll
            for (int df = 0; df < 4; df++) {
                vb0[df] = __float_as_uint(Vs[kk + 2*tig    ][df*8+gid]);
                vb1[df] = __float_as_uint(Vs[kk + 2*tig + 1][df*8+gid]);
            }
            #pragma unroll
            for (int mi = 0; mi < 2; mi++) {
                unsigned a0 = __float_as_uint(S[mi][nf][0]);
                unsigned a1 = __float_as_uint(S[mi][nf][2]);
                unsigned a2 = __float_as_uint(S[mi][nf][1]);
                unsigned a3 = __float_as_uint(S[mi][nf][3]);
                #pragma unroll
                for (int df = 0; df < 4; df++)
                    mma_tf32(Oacc[mi][df], a0, a1, a2, a3, vb0[df], vb1[df]);
            }
        }
    }

    // ---- epilogue ----
    #pragma unroll
    for (int j = 0; j < 4; j++) {
        int mi = j >> 1, half = j & 1;
        float inv = 1.f / l_run[j];
        int row = n0 + wrow + mi*16 + gid + half*8;
        float* op = o + (size_t)(b*TOKS + row)*EMB + h*32;
        #pragma unroll
        for (int df = 0; df < 4; df++) {
            *(float2*)(op + df*8 + 2*tig) =
                make_float2(Oacc[mi][df][half*2]*inv, Oacc[mi][df][half*2+1]*inv);
        }
    }
}

// ---------------- depthwise 3x3 dilation-2 conv + bias + gelu ----------------
__global__ void __launch_bounds__(256) dwconv_k(
    const float* __restrict__ hid, const float* __restrict__ wd,
    const float* __restrict__ bd, float* __restrict__ out)
{
    int bc = blockIdx.x;
    int c = bc & 511;
    __shared__ float t[32][32];
    const float* in = hid + (size_t)bc*1024;
    int tid = threadIdx.x;
    #pragma unroll
    for (int i = 0; i < 4; i++) { int p = tid + i*256; t[p>>5][p&31] = in[p]; }
    __syncthreads();
    float w[9];
    #pragma unroll
    for (int i = 0; i < 9; i++) w[i] = wd[c*9 + i];
    float bias = bd[c];
    #pragma unroll
    for (int i = 0; i < 4; i++) {
        int p = tid + i*256; int r = p >> 5, col = p & 31;
        float s = bias;
        #pragma unroll
        for (int u = 0; u < 3; u++)
            #pragma unroll
            for (int v = 0; v < 3; v++) {
                int rr = r + (u-1)*2, cc = col + (v-1)*2;
                if (rr >= 0 && rr < 32 && cc >= 0 && cc < 32)
                    s = fmaf(t[rr][cc], w[u*3+v], s);
            }
        out[(size_t)bc*1024 + p] = gelu_f(s);
    }
}

// ---------------- orchestration ----------------
extern "C" void kernel_launch(void* const* d_in, const int* in_sizes, int n_in,
                              void* d_out, int out_size)
{
    const float* x     = (const float*)d_in[0];
    const float* pw    = (const float*)d_in[1];
    const float* pb    = (const float*)d_in[2];
    const float* te    = (const float*)d_in[3];
    const float* qkvw  = (const float*)d_in[4];
    const float* projw = (const float*)d_in[5];
    const float* projb = (const float*)d_in[6];
    const float* ln1g  = (const float*)d_in[7];
    const float* ln1b  = (const float*)d_in[8];
    const float* ln2g  = (const float*)d_in[9];
    const float* ln2b  = (const float*)d_in[10];
    const float* rpbt  = (const float*)d_in[11];
    const float* gb    = (const float*)d_in[12];
    const float* pw1w  = (const float*)d_in[13];
    const float* pw1b  = (const float*)d_in[14];
    const float* dww   = (const float*)d_in[15];
    const float* dwb   = (const float*)d_in[16];
    const float* pw2w  = (const float*)d_in[17];
    const float* pw2b  = (const float*)d_in[18];
    float* tok = (float*)d_out;

    float *yb, *qkvb, *ob, *big;
    cudaGetSymbolAddress((void**)&yb,   g_y);
    cudaGetSymbolAddress((void**)&qkvb, g_qkv);
    cudaGetSymbolAddress((void**)&ob,   g_o);
    cudaGetSymbolAddress((void**)&big,  g_big);
    __nv_bfloat16* biasf = (__nv_bfloat16*)big;      // attention phase (16 MB used)
    float* hid   = big;                              // MLP phase (first half)
    float* hid2  = big + (size_t)BBATCH*HIDDEN*TOKS; // MLP phase (second half)

    patch_embed_k<<<BBATCH*TOKS, 256>>>(x, pw, pb, te, tok);

    for (int l = 0; l < NLAYER; l++) {
        // --- attention phase (g_big = bf16 biasf) ---
        biasprep_k<<<dim3(1024, 8), 256>>>(
            rpbt + (size_t)l*3969*NHEADS, gb + (size_t)l*1024*1024, biasf);
        layernorm_k<<<1024, 256>>>(tok, ln1g + l*EMB, ln1b + l*EMB, yb);
        // qkv = y @ qkv_w^T : M=8192, N=768, K=256
        gemm_tc<0><<<dim3(12, 64, 1), 256>>>(
            yb, 0, EMB,
            qkvw + (size_t)l*768*EMB, 0,
            qkvb, 0, 768, nullptr, 0, 0, 0, EMB);
        attn_k<<<dim3(8, 64), 128>>>(qkvb, biasf, ob);
        // tok += o @ proj_w^T + proj_b : M=8192, N=256, K=256
        gemm_tc<0><<<dim3(4, 64, 1), 256>>>(
            ob, 0, EMB,
            projw + (size_t)l*EMB*EMB, 0,
            tok, 0, EMB, projb + l*EMB, 0, 0, 1, EMB);

        // --- MLP phase (g_big = hid | hid2; biasf is dead now) ---
        layernorm_k<<<1024, 256>>>(tok, ln2g + l*EMB, ln2b + l*EMB, yb);
        // hid[b][c][n] = gelu(W1·Y^T + b1[c]) : per-batch M=512, N=1024, K=256
        gemm_tc<0><<<dim3(16, 4, BBATCH), 256>>>(
            pw1w + (size_t)l*HIDDEN*EMB, 0, EMB,
            yb, (size_t)TOKS*EMB,
            hid, (size_t)HIDDEN*TOKS, TOKS, pw1b + l*HIDDEN, 1, 1, 0, EMB);
        dwconv_k<<<BBATCH*HIDDEN, 256>>>(hid, dww + (size_t)l*HIDDEN*9, dwb + l*HIDDEN, hid2);
        // tok += hid2^T · W2^T + b2 : per-batch M=1024, N=256, K=512 (A transposed)
        gemm_tc<1><<<dim3(4, 8, BBATCH), 256>>>(
            hid2, (size_t)HIDDEN*TOKS, TOKS,
            pw2w + (size_t)l*EMB*HIDDEN, 0,
            tok, (size_t)TOKS*EMB, EMB, pw2b + l*EMB, 0, 0, 1, HIDDEN);
    }
}